// round 3
// baseline (speedup 1.0000x reference)
#include <cuda_runtime.h>

#define QN      400
#define PN      200000
#define NLAB    100
#define KS      2
#define THREADS 128
#define CHUNK   (PN / KS)          // 100000
#define BINS_FLOATS (NLAB * 2 * THREADS)   // 25600 floats = 100 KB

// ---------------- device scratch (no allocation allowed) ----------------
__device__ unsigned char g_lab8[PN];
__device__ float g_partial[KS * QN * NLAB * 2];   // [r][q][lab][v]
__device__ float g_totals[KS * QN * 2];           // [r][q][{f0tot, ptot}]

// ---------------- kernel 0: narrow labels to u8 ----------------
__global__ void convert_labels(const int* __restrict__ labels) {
    int i = blockIdx.x * blockDim.x + threadIdx.x;
    int base = i * 4;
    if (base < PN) {
        int4 l = *(const int4*)(labels + base);
        uchar4 u;
        u.x = (unsigned char)l.x; u.y = (unsigned char)l.y;
        u.z = (unsigned char)l.z; u.w = (unsigned char)l.w;
        *(uchar4*)(g_lab8 + base) = u;
    }
}

// ---------------- elementwise transform (exactly 3 MUFU) ----------------
__device__ __forceinline__ void proc_one(float x, int lab, int tid,
                                         float* __restrict__ sb,
                                         float& accf0, float& accp) {
    // t = e^{-|x|}
    float t   = __expf(-fabsf(x));           // FMUL + MUFU.EX2
    float opt = 1.0f + t;
    float inv = __fdividef(1.0f, opt);       // MUFU.RCP
    float lse = __logf(opt);                 // MUFU.LG2 + FMUL  ( = log(1+e^{-|x|}) )
    float logp  = fminf(x, 0.0f) - lse;      // log sigmoid(x)
    float l1mp  = logp - x;                  // log sigmoid(-x)
    float p     = (x >= 0.0f) ? inv : (1.0f - inv);
    float omp   = 1.0f - p;
    float f1 = -0.25f * (omp * omp) * logp;
    float f0 = -0.75f * (p * p) * l1mp;
    accf0 += f0;
    accp  += p;
    int b = lab * (2 * THREADS) + tid;       // [lab][0][tid]
    sb[b]           += f1 - f0;              // d-bin (conflict-free: bank = tid%32)
    sb[b + THREADS] += p;                    // s-bin
}

// ---------------- kernel 1: main segmented reduction ----------------
__global__ __launch_bounds__(THREADS, 2)
void main_kernel(const float* __restrict__ pred) {
    extern __shared__ float sb[];            // [NLAB][2][THREADS]
    const int tid = threadIdx.x;
    const int q = blockIdx.x;
    const int r = blockIdx.y;

    // zero lane-private bins
    float4* sb4 = (float4*)sb;
    #pragma unroll 4
    for (int i = tid; i < BINS_FLOATS / 4; i += THREADS)
        sb4[i] = make_float4(0.f, 0.f, 0.f, 0.f);
    __syncthreads();

    const float* row = pred + (size_t)q * PN + (size_t)r * CHUNK;
    const unsigned char* lab = g_lab8 + r * CHUNK;

    float accf0 = 0.f, accp = 0.f;
    for (int idx = tid * 4; idx < CHUNK; idx += THREADS * 4) {
        float4 x4 = *(const float4*)(row + idx);
        uchar4 l4 = *(const uchar4*)(lab + idx);
        proc_one(x4.x, (int)l4.x, tid, sb, accf0, accp);
        proc_one(x4.y, (int)l4.y, tid, sb, accf0, accp);
        proc_one(x4.z, (int)l4.z, tid, sb, accf0, accp);
        proc_one(x4.w, (int)l4.w, tid, sb, accf0, accp);
    }
    __syncthreads();

    // reduce 128 lanes per bin -> deterministic partial buffer
    for (int b = tid; b < NLAB * 2; b += THREADS) {
        int base = (b >> 1) * (2 * THREADS) + (b & 1) * THREADS;
        float s = 0.f;
        #pragma unroll 8
        for (int i = 0; i < THREADS; i++)
            s += sb[base + ((i + tid) & (THREADS - 1))];  // staggered: conflict-free
        g_partial[(r * QN + q) * NLAB * 2 + b] = s;
    }

    // row totals (f0 sum, p sum)
    #pragma unroll
    for (int off = 16; off; off >>= 1) {
        accf0 += __shfl_down_sync(0xffffffffu, accf0, off);
        accp  += __shfl_down_sync(0xffffffffu, accp,  off);
    }
    __shared__ float ws[8];
    int w = tid >> 5;
    if ((tid & 31) == 0) { ws[w * 2] = accf0; ws[w * 2 + 1] = accp; }
    __syncthreads();
    if (tid == 0) {
        float f = 0.f, pp = 0.f;
        #pragma unroll
        for (int i = 0; i < THREADS / 32; i++) { f += ws[i * 2]; pp += ws[i * 2 + 1]; }
        g_totals[(r * QN + q) * 2 + 0] = f;
        g_totals[(r * QN + q) * 2 + 1] = pp;
    }
}

// ---------------- kernel 2: counts + cost assembly ----------------
__global__ void finalize(float* __restrict__ out) {
    const int j = blockIdx.x;           // label 0..99
    const int tid = threadIdx.x;        // 256 threads

    int c = 0;
    for (int i = tid * 4; i < PN; i += 256 * 4) {
        uchar4 l4 = *(const uchar4*)(g_lab8 + i);
        c += (l4.x == j) + (l4.y == j) + (l4.z == j) + (l4.w == j);
    }
    #pragma unroll
    for (int off = 16; off; off >>= 1) c += __shfl_down_sync(0xffffffffu, c, off);
    __shared__ int cs[8];
    if ((tid & 31) == 0) cs[tid >> 5] = c;
    __syncthreads();
    int cnt = 0;
    #pragma unroll
    for (int w = 0; w < 8; w++) cnt += cs[w];
    float fc = (float)cnt;

    for (int q = tid; q < QN; q += 256) {
        float dsum = 0.f, ssum = 0.f, f0t = 0.f, pt = 0.f;
        #pragma unroll
        for (int r = 0; r < KS; r++) {
            int bi = ((r * QN + q) * NLAB + j) * 2;
            dsum += g_partial[bi];
            ssum += g_partial[bi + 1];
            f0t  += g_totals[(r * QN + q) * 2 + 0];
            pt   += g_totals[(r * QN + q) * 2 + 1];
        }
        float cmask = (dsum + f0t) * (1.0f / (float)PN);
        float dice  = 1.0f - (2.0f * ssum + 1.0f) / (pt + fc + 1.0f);
        out[q * NLAB + j] = cmask + dice;
    }
}

// ---------------- launch ----------------
extern "C" void kernel_launch(void* const* d_in, const int* in_sizes, int n_in,
                              void* d_out, int out_size) {
    const float* pred  = (const float*)d_in[0];
    const int* labels  = (const int*)d_in[1];
    float* out = (float*)d_out;

    cudaFuncSetAttribute(main_kernel,
                         cudaFuncAttributeMaxDynamicSharedMemorySize,
                         BINS_FLOATS * sizeof(float));

    convert_labels<<<(PN / 4 + 255) / 256, 256>>>(labels);
    dim3 grid(QN, KS);
    main_kernel<<<grid, THREADS, BINS_FLOATS * sizeof(float)>>>(pred);
    finalize<<<NLAB, 256>>>(out);
}

// round 4
// speedup vs baseline: 2.6192x; 2.6192x over previous
#include <cuda_runtime.h>
#include <cuda_bf16.h>

#define QN      400
#define PN      200000
#define NLAB    100
#define KS      4
#define THREADS 128
#define CHUNK   (PN / KS)                 // 50000
#define BINW    (NLAB * THREADS)          // 12800 bf16x2 bins = 50 KB

// ---------------- device scratch (no allocation allowed) ----------------
__device__ unsigned char g_lab8[PN];
__device__ float g_partial[KS * QN * NLAB * 2];   // [r][q][lab][{d,s}]
__device__ float g_totals[KS * QN * 2];           // [r][q][{f0tot, ptot}]

// ---------------- kernel 0: narrow labels to u8 ----------------
__global__ void convert_labels(const int* __restrict__ labels) {
    int i = blockIdx.x * blockDim.x + threadIdx.x;
    int base = i * 4;
    if (base < PN) {
        int4 l = *(const int4*)(labels + base);
        uchar4 u;
        u.x = (unsigned char)l.x; u.y = (unsigned char)l.y;
        u.z = (unsigned char)l.z; u.w = (unsigned char)l.w;
        *(uchar4*)(g_lab8 + base) = u;
    }
}

// ---------------- kernel 1: main segmented reduction ----------------
__global__ __launch_bounds__(THREADS, 4)
void main_kernel(const float* __restrict__ pred) {
    extern __shared__ __nv_bfloat162 sb[];   // [NLAB][THREADS], bank = tid%32
    const int tid = threadIdx.x;
    const int q = blockIdx.x;
    const int r = blockIdx.y;

    // zero bins (12800 * 4B = 3200 uint4)
    uint4* z4 = (uint4*)sb;
    #pragma unroll 4
    for (int i = tid; i < BINW / 4; i += THREADS)
        z4[i] = make_uint4(0u, 0u, 0u, 0u);
    __syncthreads();

    const float* row = pred + (size_t)q * PN + (size_t)r * CHUNK;
    const unsigned char* lab = g_lab8 + r * CHUNK;

    float accf0a = 0.f, accpa = 0.f, accf0b = 0.f, accpb = 0.f;

    for (int idx = tid * 8; idx < CHUNK; idx += THREADS * 8) {
        float4 va = __ldcs((const float4*)(row + idx));
        float4 vb = __ldcs((const float4*)(row + idx + 4));
        uchar4 l0 = *(const uchar4*)(lab + idx);
        uchar4 l1 = *(const uchar4*)(lab + idx + 4);

        float xs[8] = {va.x, va.y, va.z, va.w, vb.x, vb.y, vb.z, vb.w};
        int   ls[8] = {(int)l0.x, (int)l0.y, (int)l0.z, (int)l0.w,
                       (int)l1.x, (int)l1.y, (int)l1.z, (int)l1.w};

        __nv_bfloat162 dp[8];
        // ---- compute phase: 8 independent transform chains (3 MUFU each) ----
        #pragma unroll
        for (int i = 0; i < 8; i++) {
            float x   = xs[i];
            float t   = __expf(-fabsf(x));        // MUFU.EX2
            float opt = 1.0f + t;
            float inv = __fdividef(1.0f, opt);    // MUFU.RCP
            float lse = __logf(opt);              // MUFU.LG2
            float logp = fminf(x, 0.0f) - lse;    // log sigmoid(x)
            float l1mp = logp - x;                // log sigmoid(-x)
            float p    = (x >= 0.0f) ? inv : (1.0f - inv);
            float omp  = 1.0f - p;
            float f0 = -0.75f * (p * p) * l1mp;
            float d  = -0.25f * (omp * omp) * logp - f0;
            if (i & 1) { accf0b += f0; accpb += p; }
            else       { accf0a += f0; accpa += p; }
            dp[i] = __floats2bfloat162_rn(d, p);  // .x=d, .y=p
        }
        // ---- RMW phase: LDS.32 + HADD2 + STS.32, conflict-free, lane-private ----
        #pragma unroll
        for (int i = 0; i < 8; i++) {
            __nv_bfloat162* bp = sb + (ls[i] * THREADS + tid);
            *bp = __hadd2(*bp, dp[i]);
        }
    }
    float accf0 = accf0a + accf0b;
    float accp  = accpa  + accpb;
    __syncthreads();

    // reduce 128 lanes per label -> deterministic partial buffer (exact f32)
    for (int b = tid; b < NLAB; b += THREADS) {
        float ds = 0.f, ss = 0.f;
        #pragma unroll 4
        for (int i = 0; i < THREADS; i++) {
            float2 v = __bfloat1622float2(sb[b * THREADS + ((i + tid) & (THREADS - 1))]);
            ds += v.x; ss += v.y;
        }
        int o = ((r * QN + q) * NLAB + b) * 2;
        g_partial[o]     = ds;
        g_partial[o + 1] = ss;
    }

    // row totals (f0 sum, p sum) — exact f32 path
    #pragma unroll
    for (int off = 16; off; off >>= 1) {
        accf0 += __shfl_down_sync(0xffffffffu, accf0, off);
        accp  += __shfl_down_sync(0xffffffffu, accp,  off);
    }
    __shared__ float ws[8];
    int w = tid >> 5;
    if ((tid & 31) == 0) { ws[w * 2] = accf0; ws[w * 2 + 1] = accp; }
    __syncthreads();
    if (tid == 0) {
        float f = 0.f, pp = 0.f;
        #pragma unroll
        for (int i = 0; i < THREADS / 32; i++) { f += ws[i * 2]; pp += ws[i * 2 + 1]; }
        g_totals[(r * QN + q) * 2 + 0] = f;
        g_totals[(r * QN + q) * 2 + 1] = pp;
    }
}

// ---------------- kernel 2: counts + cost assembly ----------------
__global__ void finalize(float* __restrict__ out) {
    const int j = blockIdx.x;           // label 0..99
    const int tid = threadIdx.x;        // 256 threads

    int c = 0;
    for (int i = tid * 4; i < PN; i += 256 * 4) {
        uchar4 l4 = *(const uchar4*)(g_lab8 + i);
        c += (l4.x == j) + (l4.y == j) + (l4.z == j) + (l4.w == j);
    }
    #pragma unroll
    for (int off = 16; off; off >>= 1) c += __shfl_down_sync(0xffffffffu, c, off);
    __shared__ int cs[8];
    if ((tid & 31) == 0) cs[tid >> 5] = c;
    __syncthreads();
    int cnt = 0;
    #pragma unroll
    for (int w = 0; w < 8; w++) cnt += cs[w];
    float fc = (float)cnt;

    for (int q = tid; q < QN; q += 256) {
        float dsum = 0.f, ssum = 0.f, f0t = 0.f, pt = 0.f;
        #pragma unroll
        for (int r = 0; r < KS; r++) {
            int bi = ((r * QN + q) * NLAB + j) * 2;
            dsum += g_partial[bi];
            ssum += g_partial[bi + 1];
            f0t  += g_totals[(r * QN + q) * 2 + 0];
            pt   += g_totals[(r * QN + q) * 2 + 1];
        }
        float cmask = (dsum + f0t) * (1.0f / (float)PN);
        float dice  = 1.0f - (2.0f * ssum + 1.0f) / (pt + fc + 1.0f);
        out[q * NLAB + j] = cmask + dice;
    }
}

// ---------------- launch ----------------
extern "C" void kernel_launch(void* const* d_in, const int* in_sizes, int n_in,
                              void* d_out, int out_size) {
    const float* pred  = (const float*)d_in[0];
    const int* labels  = (const int*)d_in[1];
    float* out = (float*)d_out;

    cudaFuncSetAttribute(main_kernel,
                         cudaFuncAttributeMaxDynamicSharedMemorySize,
                         BINW * (int)sizeof(__nv_bfloat162));

    convert_labels<<<(PN / 4 + 255) / 256, 256>>>(labels);
    dim3 grid(QN, KS);
    main_kernel<<<grid, THREADS, BINW * sizeof(__nv_bfloat162)>>>(pred);
    finalize<<<NLAB, 256>>>(out);
}

// round 5
// speedup vs baseline: 3.1879x; 1.2172x over previous
#include <cuda_runtime.h>
#include <cuda_bf16.h>

#define QN      400
#define PN      200000
#define NLAB    100
#define KS      4
#define THREADS 128
#define CHUNK   (PN / KS)                 // 50000
#define BINW    (NLAB * THREADS)          // 12800 bf16x2 bins = 50 KB
#define CVT_BLOCKS ((PN / 4 + 255) / 256) // 196

// ---------------- device scratch (no allocation allowed) ----------------
__device__ unsigned char g_lab8[PN];
__device__ int   g_blockhist[CVT_BLOCKS * NLAB];
__device__ float g_partial[KS * QN * NLAB * 2];   // [r][q][lab][{d,s}]
__device__ float g_totals[KS * QN * 2];           // [r][q][{f0tot, ptot}]

// ---------------- kernel 0: narrow labels to u8 + per-block histogram ----------------
__global__ void convert_labels(const int* __restrict__ labels) {
    __shared__ int hist[NLAB];
    const int tid = threadIdx.x;
    for (int i = tid; i < NLAB; i += 256) hist[i] = 0;
    __syncthreads();

    int i = blockIdx.x * blockDim.x + tid;
    int base = i * 4;
    if (base < PN) {
        int4 l = *(const int4*)(labels + base);
        uchar4 u;
        u.x = (unsigned char)l.x; u.y = (unsigned char)l.y;
        u.z = (unsigned char)l.z; u.w = (unsigned char)l.w;
        *(uchar4*)(g_lab8 + base) = u;
        atomicAdd(&hist[l.x], 1); atomicAdd(&hist[l.y], 1);
        atomicAdd(&hist[l.z], 1); atomicAdd(&hist[l.w], 1);
    }
    __syncthreads();
    for (int j = tid; j < NLAB; j += 256)
        g_blockhist[blockIdx.x * NLAB + j] = hist[j];
}

// ---------------- elementwise transform (exactly 3 MUFU) ----------------
__device__ __forceinline__ void xform(float x, float& d, float& p, float& f0) {
    float t   = __expf(-fabsf(x));        // MUFU.EX2
    float opt = 1.0f + t;
    float inv = __fdividef(1.0f, opt);    // MUFU.RCP
    float lse = __logf(opt);              // MUFU.LG2
    float logp = fminf(x, 0.0f) - lse;    // log sigmoid(x)
    float l1mp = logp - x;                // log sigmoid(-x)
    p = (x >= 0.0f) ? inv : (1.0f - inv);
    float omp = 1.0f - p;
    f0 = -0.75f * (p * p) * l1mp;
    d  = -0.25f * (omp * omp) * logp - f0;
}

// ---------------- kernel 1: main segmented reduction ----------------
__global__ __launch_bounds__(THREADS, 4)
void main_kernel(const float* __restrict__ pred) {
    extern __shared__ __nv_bfloat162 sb[];   // [NLAB][THREADS], bank = tid%32
    const int tid = threadIdx.x;
    const int q = blockIdx.x;
    const int r = blockIdx.y;

    uint4* z4 = (uint4*)sb;
    #pragma unroll 4
    for (int i = tid; i < BINW / 4; i += THREADS)
        z4[i] = make_uint4(0u, 0u, 0u, 0u);
    __syncthreads();

    const float* row = pred + (size_t)q * PN + (size_t)r * CHUNK;
    const unsigned char* lab = g_lab8 + r * CHUNK;

    float accf0a = 0.f, accpa = 0.f, accf0b = 0.f, accpb = 0.f;

    // ---- prefetch first iteration ----
    int idx = tid * 8;
    float4 va, vb; uint2 lw;
    if (idx < CHUNK) {
        va = __ldcs((const float4*)(row + idx));
        vb = __ldcs((const float4*)(row + idx + 4));
        lw = *(const uint2*)(lab + idx);
    }

    while (idx < CHUNK) {
        // ---- issue next iteration's loads before consuming current ----
        int nidx = idx + THREADS * 8;
        float4 nva, nvb; uint2 nlw;
        if (nidx < CHUNK) {
            nva = __ldcs((const float4*)(row + nidx));
            nvb = __ldcs((const float4*)(row + nidx + 4));
            nlw = *(const uint2*)(lab + nidx);
        }

        float xs[8] = {va.x, va.y, va.z, va.w, vb.x, vb.y, vb.z, vb.w};
        int   ls[8];
        #pragma unroll
        for (int i = 0; i < 4; i++) {
            ls[i]     = (int)((lw.x >> (8 * i)) & 0xffu);
            ls[i + 4] = (int)((lw.y >> (8 * i)) & 0xffu);
        }

        __nv_bfloat162 dp[8];
        #pragma unroll
        for (int i = 0; i < 8; i++) {
            float d, p, f0;
            xform(xs[i], d, p, f0);
            if (i & 1) { accf0b += f0; accpb += p; }
            else       { accf0a += f0; accpa += p; }
            dp[i] = __floats2bfloat162_rn(d, p);  // .x=d, .y=p
        }
        // RMW phase: LDS.32 + HADD2 + STS.32, conflict-free lanes
        #pragma unroll
        for (int i = 0; i < 8; i++) {
            __nv_bfloat162* bp = sb + (ls[i] * THREADS + tid);
            *bp = __hadd2(*bp, dp[i]);
        }

        va = nva; vb = nvb; lw = nlw;
        idx = nidx;
    }
    float accf0 = accf0a + accf0b;
    float accp  = accpa  + accpb;
    __syncthreads();

    // reduce 128 lanes per label -> deterministic partial buffer (exact f32)
    for (int b = tid; b < NLAB; b += THREADS) {
        float ds = 0.f, ss = 0.f;
        #pragma unroll 4
        for (int i = 0; i < THREADS; i++) {
            float2 v = __bfloat1622float2(sb[b * THREADS + ((i + tid) & (THREADS - 1))]);
            ds += v.x; ss += v.y;
        }
        int o = ((r * QN + q) * NLAB + b) * 2;
        g_partial[o]     = ds;
        g_partial[o + 1] = ss;
    }

    // row totals (f0 sum, p sum) — exact f32 path
    #pragma unroll
    for (int off = 16; off; off >>= 1) {
        accf0 += __shfl_down_sync(0xffffffffu, accf0, off);
        accp  += __shfl_down_sync(0xffffffffu, accp,  off);
    }
    __shared__ float ws[8];
    int w = tid >> 5;
    if ((tid & 31) == 0) { ws[w * 2] = accf0; ws[w * 2 + 1] = accp; }
    __syncthreads();
    if (tid == 0) {
        float f = 0.f, pp = 0.f;
        #pragma unroll
        for (int i = 0; i < THREADS / 32; i++) { f += ws[i * 2]; pp += ws[i * 2 + 1]; }
        g_totals[(r * QN + q) * 2 + 0] = f;
        g_totals[(r * QN + q) * 2 + 1] = pp;
    }
}

// ---------------- kernel 2: counts + cost assembly ----------------
__global__ void finalize(float* __restrict__ out) {
    const int j = blockIdx.x;           // label 0..99
    const int tid = threadIdx.x;        // 256 threads

    // count for label j: sum per-block histograms (196 ints)
    int c = 0;
    for (int b = tid; b < CVT_BLOCKS; b += 256)
        c += g_blockhist[b * NLAB + j];
    #pragma unroll
    for (int off = 16; off; off >>= 1) c += __shfl_down_sync(0xffffffffu, c, off);
    __shared__ int cs[8];
    if ((tid & 31) == 0) cs[tid >> 5] = c;
    __syncthreads();
    int cnt = 0;
    #pragma unroll
    for (int w = 0; w < 8; w++) cnt += cs[w];
    float fc = (float)cnt;

    for (int q = tid; q < QN; q += 256) {
        float dsum = 0.f, ssum = 0.f, f0t = 0.f, pt = 0.f;
        #pragma unroll
        for (int r = 0; r < KS; r++) {
            int bi = ((r * QN + q) * NLAB + j) * 2;
            dsum += g_partial[bi];
            ssum += g_partial[bi + 1];
            f0t  += g_totals[(r * QN + q) * 2 + 0];
            pt   += g_totals[(r * QN + q) * 2 + 1];
        }
        float cmask = (dsum + f0t) * (1.0f / (float)PN);
        float dice  = 1.0f - (2.0f * ssum + 1.0f) / (pt + fc + 1.0f);
        out[q * NLAB + j] = cmask + dice;
    }
}

// ---------------- launch ----------------
extern "C" void kernel_launch(void* const* d_in, const int* in_sizes, int n_in,
                              void* d_out, int out_size) {
    const float* pred  = (const float*)d_in[0];
    const int* labels  = (const int*)d_in[1];
    float* out = (float*)d_out;

    cudaFuncSetAttribute(main_kernel,
                         cudaFuncAttributeMaxDynamicSharedMemorySize,
                         BINW * (int)sizeof(__nv_bfloat162));

    convert_labels<<<CVT_BLOCKS, 256>>>(labels);
    dim3 grid(QN, KS);
    main_kernel<<<grid, THREADS, BINW * sizeof(__nv_bfloat162)>>>(pred);
    finalize<<<NLAB, 256>>>(out);
}